// round 16
// baseline (speedup 1.0000x reference)
#include <cuda_runtime.h>
#include <cstdint>

#define BB 4
#define NN 4096
#define DD 1024
#define EE 64
#define CAP 128
#define NT (BB*NN)                       // 16384 tokens
#define BNEC ((size_t)NT*EE*CAP)         // 134217728 elements per big tensor
#define THRESH 0.2f
#define NB 256                           // gating blocks (64 tokens each)

// zero-fill partition (in float4 units): total = 2*BNEC/4 = 67,108,864
#define TOT4   67108864UL
#define K2Z4   12582912UL                // 192 MiB handled during scan window
#define K1Z4   (TOT4 - K2Z4)             // 54,525,952 float4 (832 MiB)
#define NZB    26624                     // K1 zero blocks: 26624 * 2048 = K1Z4
#define K2ZB   6144                      // K2 zero blocks: 6144 * 2048 = K2Z4

#define CP_ASYNC16(dst_u32, src_ptr) \
    asm volatile("cp.async.cg.shared.global [%0], [%1], 16;" :: "r"(dst_u32), "l"(src_ptr) : "memory")
#define CP_COMMIT() asm volatile("cp.async.commit_group;" ::: "memory")
#define CP_WAIT(n)  asm volatile("cp.async.wait_group %0;" :: "n"(n) : "memory")

// ---------------- scratch (no allocations allowed) ----------------
__device__ int   g_idx1[NT], g_idx2[NT];
__device__ float g_g1[NT],  g_g2[NT];
__device__ int   g_pos1[NT], g_pos2[NT];
__device__ float g_dens_p[NB][EE];       // per-gating-block partials (no atomics, no init)
__device__ int   g_cnt_p[NB][EE];        // per-chunk top-1 histogram (scan input)
__device__ int   g_cnt2_p[NB][EE];       // per-chunk thresholded top-2 histogram
__device__ float g_lse_p[NB];

// ---------------- K1: heterogeneous blocks (R13-proven) ----------------
// bid < NB   : GEMM (4-stage cp.async pipeline) + softmax + top2 + aux + histograms
// bid >= NB  : pure zero-writer block, contiguous 32 KiB (proven 85.7%-DRAM pattern)
__global__ __launch_bounds__(256) void fused_kernel(const float* __restrict__ x,
                                                    const float* __restrict__ w,
                                                    float* __restrict__ out) {
    const int tid = threadIdx.x;
    const int bid = blockIdx.x;

    // ======== zero-writer blocks ========
    if (bid >= NB) {
        const size_t base = (size_t)(bid - NB) * 2048 + tid;
        float4* __restrict__ o4 = (float4*)out;
        const float4 z4 = make_float4(0.f, 0.f, 0.f, 0.f);
        #pragma unroll
        for (int i = 0; i < 8; i++)
            __stcs(&o4[base + (size_t)i * 256], z4);
        return;
    }

    // ======== GEMM blocks: 64 tokens x 64 experts, pipelined loads ========
    __shared__ union {
        struct {
            float xs[4][64][16];   // [stage][token][k-within-chunk]
            float ws[4][16][64];   // [stage][k][expert]
        } p;
        struct {
            float logits[64][65];  // padded; overwritten in-place by probs
            float sm_invS[64];
            int   scnt[64];
            int   scnt2[64];
        } g;
    } sm;

    const int t0 = bid * 64;
    const int eg = tid & 15, tg = tid >> 4;

    float acc[4][4];
    #pragma unroll
    for (int i = 0; i < 4; i++)
        #pragma unroll
        for (int j = 0; j < 4; j++) acc[i][j] = 0.f;

    const int xtok = tid >> 2, xkq = tid & 3;   // x loader: 64 tok x 4 quads
    const int wkk  = tid >> 4, weq = tid & 15;  // w loader: 16 k x 16 quads

    const float4* xg = (const float4*)(x) + (size_t)(t0 + xtok) * (DD/4) + xkq;
    const float4* wg = (const float4*)(w) + (size_t)wkk * (EE/4) + weq;

    uint32_t xdst[4], wdst[4];
    #pragma unroll
    for (int s = 0; s < 4; s++) {
        xdst[s] = (uint32_t)__cvta_generic_to_shared(&sm.p.xs[s][xtok][xkq*4]);
        wdst[s] = (uint32_t)__cvta_generic_to_shared(&sm.p.ws[s][wkk][weq*4]);
    }

    #pragma unroll
    for (int p = 0; p < 3; p++) {
        CP_ASYNC16(xdst[p], xg + (size_t)p * 4);
        CP_ASYNC16(wdst[p], wg + (size_t)p * 16 * (EE/4));
        CP_COMMIT();
    }

    for (int kc = 0; kc < DD/16; kc++) {
        CP_WAIT(2);
        __syncthreads();
        if (kc + 3 < DD/16) {
            const int s = (kc + 3) & 3;
            CP_ASYNC16(xdst[s], xg + (size_t)(kc + 3) * 4);
            CP_ASYNC16(wdst[s], wg + (size_t)(kc + 3) * 16 * (EE/4));
        }
        CP_COMMIT();

        const int s = kc & 3;
        #pragma unroll
        for (int kq = 0; kq < 4; kq++) {
            float4 av[4];
            #pragma unroll
            for (int i = 0; i < 4; i++)
                av[i] = *(const float4*)&sm.p.xs[s][tg*4 + i][kq*4];
            #pragma unroll
            for (int kk = 0; kk < 4; kk++) {
                const float4 bv = *(const float4*)&sm.p.ws[s][kq*4 + kk][eg*4];
                #pragma unroll
                for (int i = 0; i < 4; i++) {
                    const float ai = ((const float*)&av[i])[kk];
                    acc[i][0] += ai * bv.x;
                    acc[i][1] += ai * bv.y;
                    acc[i][2] += ai * bv.z;
                    acc[i][3] += ai * bv.w;
                }
            }
        }
    }

    CP_WAIT(0);
    __syncthreads();            // pipeline dead; union may flip to gating

    #pragma unroll
    for (int i = 0; i < 4; i++)
        #pragma unroll
        for (int j = 0; j < 4; j++)
            sm.g.logits[tg*4 + i][eg*4 + j] = acc[i][j];

    if (tid < 64) { sm.g.scnt[tid] = 0; sm.g.scnt2[tid] = 0; }
    __syncthreads();

    float my_lse = 0.f;
    if (tid < 64) {
        const int t = tid;
        // top-2 over logits (softmax monotonic; strict > keeps first index on ties)
        float best1 = -3.4e38f, best2 = -3.4e38f;
        int i1 = 0, i2 = 0;
        #pragma unroll 4
        for (int e = 0; e < EE; e++) {
            float l = sm.g.logits[t][e];
            if (l > best1) { best2 = best1; i2 = i1; best1 = l; i1 = e; }
            else if (l > best2) { best2 = l; i2 = e; }
        }
        float S = 0.f;
        #pragma unroll 4
        for (int e = 0; e < EE; e++) {
            float p = __expf(sm.g.logits[t][e] - best1);
            sm.g.logits[t][e] = p;               // in-place: row t owned by thread t
            S += p;
        }
        float invS = 1.0f / S;
        sm.g.sm_invS[t] = invS;
        float g1 = invS;                         // exp(best1-best1)*invS
        float g2 = __expf(best2 - best1) * invS;
        float denom = g1 + g2 + 1e-9f;
        float g1n = g1 / denom, g2n = g2 / denom;
        g_idx1[t0 + t] = i1;
        g_idx2[t0 + t] = i2;
        g_g1[t0 + t] = g1n;
        g_g2[t0 + t] = g2n;
        atomicAdd(&sm.g.scnt[i1], 1);
        if (g2n > THRESH) atomicAdd(&sm.g.scnt2[i2], 1);
        my_lse = best1 + __logf(S);
    }
    __syncthreads();

    if (tid < 64) {
        // density: column sums of the in-place prob matrix
        float s = 0.f;
        #pragma unroll 4
        for (int t = 0; t < 64; t++) s += sm.g.logits[t][tid] * sm.g.sm_invS[t];
        g_dens_p[bid][tid] = s;
        g_cnt_p[bid][tid]  = sm.g.scnt[tid];
        g_cnt2_p[bid][tid] = sm.g.scnt2[tid];
        // warp-reduce lse across the 2 warps holding tid<64
        #pragma unroll
        for (int o = 16; o > 0; o >>= 1)
            my_lse += __shfl_down_sync(0xffffffffu, my_lse, o);
        if ((tid & 31) == 0) {
            if (tid == 0) sm.g.sm_invS[0] = my_lse;   // reuse smem slot
            else          sm.g.sm_invS[1] = my_lse;
        }
    }
    __syncthreads();
    if (tid == 0) g_lse_p[bid] = sm.g.sm_invS[0] + sm.g.sm_invS[1];
}

// ---------------- K2: chunk-parallel scan (blocks 0..3, 256t) + zero-fill (4.., 256t writer shape) ----------------
__global__ __launch_bounds__(256) void scan_zero_kernel(float* __restrict__ out) {
    const int tid = threadIdx.x;

    // ---- zero-fill blocks: last 192 MiB, proven 256-thread/32KiB writer shape ----
    if (blockIdx.x >= 4) {
        const size_t base = K1Z4 + (size_t)(blockIdx.x - 4) * 2048 + tid;
        float4* __restrict__ o4 = (float4*)out;
        const float4 z4 = make_float4(0.f, 0.f, 0.f, 0.f);
        #pragma unroll
        for (int i = 0; i < 8; i++)
            __stcs(&o4[base + (size_t)i * 256], z4);
        return;
    }

    // ---- scan blocks (one per batch), 256 threads, 16 passes of 256 tokens ----
    __shared__ int s_c1[64][64];     // chunk-hist, overwritten in-place by exclusive prefix
    __shared__ int s_c2[64][64];
    __shared__ int hist1[4][64];     // per-pass lower-half-warp histograms (4 chunks/pass)
    __shared__ int hist2[4][64];

    const int b    = blockIdx.x;
    const int wid  = tid >> 5;
    const int lane = tid & 31;
    const unsigned lt = (1u << lane) - 1u;

    // load 64 chunks x 64 experts (int4-coalesced, 4 per thread)
    #pragma unroll
    for (int i = 0; i < 4; i++) {
        ((int4*)s_c1)[i*256 + tid] = ((const int4*)g_cnt_p)[b*1024 + i*256 + tid];
        ((int4*)s_c2)[i*256 + tid] = ((const int4*)g_cnt2_p)[b*1024 + i*256 + tid];
    }
    __syncthreads();

    // per-expert exclusive prefix over chunks; phase-2 base = capped phase-1 total
    if (tid < 64) {
        int run = 0;
        #pragma unroll 8
        for (int c = 0; c < 64; c++) { int v = s_c1[c][tid]; s_c1[c][tid] = run; run += v; }
        int run2 = min(run, CAP);
        #pragma unroll 8
        for (int c = 0; c < 64; c++) { int v = s_c2[c][tid]; s_c2[c][tid] = run2; run2 += v; }
    }
    __syncthreads();

    // 16 passes x 256 tokens; each 64-token chunk spans exactly 2 warps
    for (int pass = 0; pass < 16; pass++) {
        const int li = pass * 256 + tid;     // token index within batch
        const int t  = b * NN + li;
        const int ch = li >> 6;              // chunk within batch (0..63)
        const int hc = tid >> 6;             // chunk within this pass (0..3)
        const bool upper = (wid & 1);

        ((int*)hist1)[tid] = 0;              // 4*64 = 256 entries
        ((int*)hist2)[tid] = 0;
        __syncthreads();

        const int e1   = g_idx1[t];
        const bool v2  = g_g2[t] > THRESH;
        const int e2   = v2 ? g_idx2[t] : -1;

        unsigned m1 = __match_any_sync(0xffffffffu, e1);
        int r1 = __popc(m1 & lt);
        unsigned m2 = __match_any_sync(0xffffffffu, e2);
        int r2 = __popc(m2 & lt);

        if (!upper) {
            if (r1 == 0) hist1[hc][e1] = __popc(m1);
            if (v2 && r2 == 0) hist2[hc][e2] = __popc(m2);
        }
        __syncthreads();

        if (upper) {
            r1 += hist1[hc][e1];
            if (v2) r2 += hist2[hc][e2];
        }

        int p1 = s_c1[ch][e1] + r1;
        g_pos1[t] = (p1 < CAP) ? p1 : -1;
        if (v2) {
            int p2 = s_c2[ch][e2] + r2;
            g_pos2[t] = (p2 < CAP) ? p2 : -1;
        } else {
            g_pos2[t] = -1;
        }
        __syncthreads();
    }
}

// ---------------- K3: scatter nonzeros + finalize scalars (block 0) ----------------
__global__ __launch_bounds__(256) void scatter_finalize_kernel(float* __restrict__ out) {
    const int t = blockIdx.x * 256 + threadIdx.x;

    if (t < NT) {
        const int p1 = g_pos1[t], p2 = g_pos2[t];
        const size_t row = (size_t)t * (EE*CAP);

        if (p1 >= 0) {
            const size_t o = row + (size_t)g_idx1[t] * CAP + p1;
            out[o]        = 1.f;       // dispatch
            out[BNEC + o] = g_g1[t];   // combine
        }
        if (p2 >= 0) {
            const size_t o = row + (size_t)g_idx2[t] * CAP + p2;
            out[o]        = 1.f;
            out[BNEC + o] = g_g2[t];
        }
    }

    if (blockIdx.x == 0) {
        __shared__ float red[256];
        const int tid = threadIdx.x;
        const int b = tid >> 6, e = tid & 63;

        // reconstruct per-(batch,expert) dens & count from the 64 chunk partials
        float dens = 0.f; int cnt = 0;
        #pragma unroll 8
        for (int c = 0; c < 64; c++) {
            dens += g_dens_p[b*64 + c][e];
            cnt  += g_cnt_p[b*64 + c][e];
        }
        red[tid] = dens * (float)cnt;
        __syncthreads();
        for (int s = 128; s > 0; s >>= 1) {
            if (tid < s) red[tid] += red[tid + s];
            __syncthreads();
        }
        float loss = red[0] * ((float)EE / ((float)BB * (float)NN * (float)NN));
        __syncthreads();

        red[tid] = g_lse_p[tid];
        __syncthreads();
        for (int s = 128; s > 0; s >>= 1) {
            if (tid < s) red[tid] += red[tid + s];
            __syncthreads();
        }
        if (tid == 0) {
            out[2*BNEC]     = loss;
            out[2*BNEC + 1] = red[0] * (1.0f / (float)BB);
        }
    }
}

// ---------------- launch ----------------
extern "C" void kernel_launch(void* const* d_in, const int* in_sizes, int n_in,
                              void* d_out, int out_size) {
    const float* x = (const float*)d_in[0];   // [4,4096,1024] f32
    const float* w = (const float*)d_in[1];   // [1024,64] f32
    float* out = (float*)d_out;               // dispatch | combine | loss | z_loss

    fused_kernel<<<NB + NZB, 256>>>(x, w, out);
    scan_zero_kernel<<<4 + K2ZB, 256>>>(out);
    scatter_finalize_kernel<<<NT/256, 256>>>(out);
}

// round 17
// speedup vs baseline: 1.0136x; 1.0136x over previous
#include <cuda_runtime.h>
#include <cstdint>

#define BB 4
#define NN 4096
#define DD 1024
#define EE 64
#define CAP 128
#define NT (BB*NN)                       // 16384 tokens
#define BNEC ((size_t)NT*EE*CAP)         // 134217728 elements per big tensor
#define THRESH 0.2f
#define NB 256                           // gating blocks (64 tokens each)

// ALL zero-fill lives in K1: total = 2*BNEC/4 = 67,108,864 float4
#define TOT4   67108864UL
#define NZB    32768                     // 32768 * 2048 = TOT4

#define CP_ASYNC16(dst_u32, src_ptr) \
    asm volatile("cp.async.cg.shared.global [%0], [%1], 16;" :: "r"(dst_u32), "l"(src_ptr) : "memory")
#define CP_COMMIT() asm volatile("cp.async.commit_group;" ::: "memory")
#define CP_WAIT(n)  asm volatile("cp.async.wait_group %0;" :: "n"(n) : "memory")

// ---------------- scratch (no allocations allowed) ----------------
__device__ int   g_idx1[NT], g_idx2[NT];
__device__ float g_g1[NT],  g_g2[NT];
__device__ float g_dens_p[NB][EE];       // per-gating-block partials (no atomics, no init)
__device__ int   g_cnt_p[NB][EE];        // per-chunk top-1 histogram (scan input)
__device__ int   g_cnt2_p[NB][EE];       // per-chunk thresholded top-2 histogram
__device__ float g_lse_p[NB];

// ---------------- K1: heterogeneous blocks (R13-proven GEMM + writers) ----------------
// bid < NB   : GEMM (4-stage cp.async pipeline) + softmax + top2 + aux + histograms
// bid >= NB  : pure zero-writer block, contiguous 32 KiB (proven 85.7%-DRAM pattern)
__global__ __launch_bounds__(256) void fused_kernel(const float* __restrict__ x,
                                                    const float* __restrict__ w,
                                                    float* __restrict__ out) {
    const int tid = threadIdx.x;
    const int bid = blockIdx.x;

    // ======== zero-writer blocks: cover the ENTIRE output ========
    if (bid >= NB) {
        const size_t base = (size_t)(bid - NB) * 2048 + tid;
        float4* __restrict__ o4 = (float4*)out;
        const float4 z4 = make_float4(0.f, 0.f, 0.f, 0.f);
        #pragma unroll
        for (int i = 0; i < 8; i++)
            __stcs(&o4[base + (size_t)i * 256], z4);
        return;
    }

    // ======== GEMM blocks: 64 tokens x 64 experts, pipelined loads ========
    __shared__ union {
        struct {
            float xs[4][64][16];   // [stage][token][k-within-chunk]
            float ws[4][16][64];   // [stage][k][expert]
        } p;
        struct {
            float logits[64][65];  // padded; overwritten in-place by probs
            float sm_invS[64];
            int   scnt[64];
            int   scnt2[64];
        } g;
    } sm;

    const int t0 = bid * 64;
    const int eg = tid & 15, tg = tid >> 4;

    float acc[4][4];
    #pragma unroll
    for (int i = 0; i < 4; i++)
        #pragma unroll
        for (int j = 0; j < 4; j++) acc[i][j] = 0.f;

    const int xtok = tid >> 2, xkq = tid & 3;   // x loader: 64 tok x 4 quads
    const int wkk  = tid >> 4, weq = tid & 15;  // w loader: 16 k x 16 quads

    const float4* xg = (const float4*)(x) + (size_t)(t0 + xtok) * (DD/4) + xkq;
    const float4* wg = (const float4*)(w) + (size_t)wkk * (EE/4) + weq;

    uint32_t xdst[4], wdst[4];
    #pragma unroll
    for (int s = 0; s < 4; s++) {
        xdst[s] = (uint32_t)__cvta_generic_to_shared(&sm.p.xs[s][xtok][xkq*4]);
        wdst[s] = (uint32_t)__cvta_generic_to_shared(&sm.p.ws[s][wkk][weq*4]);
    }

    #pragma unroll
    for (int p = 0; p < 3; p++) {
        CP_ASYNC16(xdst[p], xg + (size_t)p * 4);
        CP_ASYNC16(wdst[p], wg + (size_t)p * 16 * (EE/4));
        CP_COMMIT();
    }

    for (int kc = 0; kc < DD/16; kc++) {
        CP_WAIT(2);
        __syncthreads();
        if (kc + 3 < DD/16) {
            const int s = (kc + 3) & 3;
            CP_ASYNC16(xdst[s], xg + (size_t)(kc + 3) * 4);
            CP_ASYNC16(wdst[s], wg + (size_t)(kc + 3) * 16 * (EE/4));
        }
        CP_COMMIT();

        const int s = kc & 3;
        #pragma unroll
        for (int kq = 0; kq < 4; kq++) {
            float4 av[4];
            #pragma unroll
            for (int i = 0; i < 4; i++)
                av[i] = *(const float4*)&sm.p.xs[s][tg*4 + i][kq*4];
            #pragma unroll
            for (int kk = 0; kk < 4; kk++) {
                const float4 bv = *(const float4*)&sm.p.ws[s][kq*4 + kk][eg*4];
                #pragma unroll
                for (int i = 0; i < 4; i++) {
                    const float ai = ((const float*)&av[i])[kk];
                    acc[i][0] += ai * bv.x;
                    acc[i][1] += ai * bv.y;
                    acc[i][2] += ai * bv.z;
                    acc[i][3] += ai * bv.w;
                }
            }
        }
    }

    CP_WAIT(0);
    __syncthreads();            // pipeline dead; union may flip to gating

    #pragma unroll
    for (int i = 0; i < 4; i++)
        #pragma unroll
        for (int j = 0; j < 4; j++)
            sm.g.logits[tg*4 + i][eg*4 + j] = acc[i][j];

    if (tid < 64) { sm.g.scnt[tid] = 0; sm.g.scnt2[tid] = 0; }
    __syncthreads();

    float my_lse = 0.f;
    if (tid < 64) {
        const int t = tid;
        // top-2 over logits (softmax monotonic; strict > keeps first index on ties)
        float best1 = -3.4e38f, best2 = -3.4e38f;
        int i1 = 0, i2 = 0;
        #pragma unroll 4
        for (int e = 0; e < EE; e++) {
            float l = sm.g.logits[t][e];
            if (l > best1) { best2 = best1; i2 = i1; best1 = l; i1 = e; }
            else if (l > best2) { best2 = l; i2 = e; }
        }
        float S = 0.f;
        #pragma unroll 4
        for (int e = 0; e < EE; e++) {
            float p = __expf(sm.g.logits[t][e] - best1);
            sm.g.logits[t][e] = p;               // in-place: row t owned by thread t
            S += p;
        }
        float invS = 1.0f / S;
        sm.g.sm_invS[t] = invS;
        float g1 = invS;                         // exp(best1-best1)*invS
        float g2 = __expf(best2 - best1) * invS;
        float denom = g1 + g2 + 1e-9f;
        float g1n = g1 / denom, g2n = g2 / denom;
        g_idx1[t0 + t] = i1;
        g_idx2[t0 + t] = i2;
        g_g1[t0 + t] = g1n;
        g_g2[t0 + t] = g2n;
        atomicAdd(&sm.g.scnt[i1], 1);
        if (g2n > THRESH) atomicAdd(&sm.g.scnt2[i2], 1);
        my_lse = best1 + __logf(S);
    }
    __syncthreads();

    if (tid < 64) {
        // density: column sums of the in-place prob matrix
        float s = 0.f;
        #pragma unroll 4
        for (int t = 0; t < 64; t++) s += sm.g.logits[t][tid] * sm.g.sm_invS[t];
        g_dens_p[bid][tid] = s;
        g_cnt_p[bid][tid]  = sm.g.scnt[tid];
        g_cnt2_p[bid][tid] = sm.g.scnt2[tid];
        // warp-reduce lse across the 2 warps holding tid<64
        #pragma unroll
        for (int o = 16; o > 0; o >>= 1)
            my_lse += __shfl_down_sync(0xffffffffu, my_lse, o);
        if ((tid & 31) == 0) {
            if (tid == 0) sm.g.sm_invS[0] = my_lse;   // reuse smem slot
            else          sm.g.sm_invS[1] = my_lse;
        }
    }
    __syncthreads();
    if (tid == 0) g_lse_p[bid] = sm.g.sm_invS[0] + sm.g.sm_invS[1];
}

// ---------------- K2: scan + INLINE scatter (blocks 0..3) + finalize (block 4) ----------------
// All zeros were written by K1 (kernel boundary orders them) -> no race; the
// scan blocks write the <=2 nonzeros per token directly. ~7us total.
__global__ __launch_bounds__(1024) void scan_scatter_kernel(float* __restrict__ out) {
    const int tid = threadIdx.x;

    // ---- finalize block (scalars live beyond 2*BNEC) ----
    if (blockIdx.x == 4) {
        if (tid < 256) {
            __shared__ float red[256];
            const int b = tid >> 6, e = tid & 63;

            float dens = 0.f; int cnt = 0;
            #pragma unroll 8
            for (int c = 0; c < 64; c++) {
                dens += g_dens_p[b*64 + c][e];
                cnt  += g_cnt_p[b*64 + c][e];
            }
            red[tid] = dens * (float)cnt;
            for (int s = 128; s > 0; s >>= 1) {
                asm volatile("bar.sync 1, 256;" ::: "memory");
                if (tid < s) red[tid] += red[tid + s];
            }
            asm volatile("bar.sync 1, 256;" ::: "memory");
            float loss = red[0] * ((float)EE / ((float)BB * (float)NN * (float)NN));
            asm volatile("bar.sync 1, 256;" ::: "memory");

            red[tid] = g_lse_p[tid];
            for (int s = 128; s > 0; s >>= 1) {
                asm volatile("bar.sync 1, 256;" ::: "memory");
                if (tid < s) red[tid] += red[tid + s];
            }
            asm volatile("bar.sync 1, 256;" ::: "memory");
            if (tid == 0) {
                out[2*BNEC]     = loss;
                out[2*BNEC + 1] = red[0] * (1.0f / (float)BB);
            }
        }
        return;
    }

    // ---- scan + scatter blocks (one per batch) ----
    __shared__ int s_c1[64][64];     // chunk-hist, overwritten in-place by exclusive prefix
    __shared__ int s_c2[64][64];
    __shared__ int hist1[16][64];    // per-pass lower-half-warp histograms
    __shared__ int hist2[16][64];

    const int b    = blockIdx.x;
    const int wid  = tid >> 5;
    const int lane = tid & 31;
    const unsigned lt = (1u << lane) - 1u;

    // load 64 chunks x 64 experts (int4-coalesced)
    ((int4*)s_c1)[tid] = ((const int4*)g_cnt_p)[b*1024 + tid];
    ((int4*)s_c2)[tid] = ((const int4*)g_cnt2_p)[b*1024 + tid];
    __syncthreads();

    // per-expert exclusive prefix over chunks; phase-2 base = capped phase-1 total
    if (tid < 64) {
        int run = 0;
        #pragma unroll 8
        for (int c = 0; c < 64; c++) { int v = s_c1[c][tid]; s_c1[c][tid] = run; run += v; }
        int run2 = min(run, CAP);
        #pragma unroll 8
        for (int c = 0; c < 64; c++) { int v = s_c2[c][tid]; s_c2[c][tid] = run2; run2 += v; }
    }
    __syncthreads();

    // 4 passes x 1024 tokens; each 64-token chunk spans exactly 2 warps
    for (int pass = 0; pass < 4; pass++) {
        const int li = pass * 1024 + tid;    // token index within batch
        const int t  = b * NN + li;
        const int ch = li >> 6;              // chunk within batch (0..63)
        const int hc = tid >> 6;             // chunk within this pass (0..15)
        const bool upper = (wid & 1);

        ((int*)hist1)[tid] = 0;
        ((int*)hist2)[tid] = 0;
        __syncthreads();

        const int e1    = g_idx1[t];
        const float g2v = g_g2[t];
        const bool v2   = g2v > THRESH;
        const int e2    = v2 ? g_idx2[t] : -1;

        unsigned m1 = __match_any_sync(0xffffffffu, e1);
        int r1 = __popc(m1 & lt);
        unsigned m2 = __match_any_sync(0xffffffffu, e2);
        int r2 = __popc(m2 & lt);

        if (!upper) {
            if (r1 == 0) hist1[hc][e1] = __popc(m1);
            if (v2 && r2 == 0) hist2[hc][e2] = __popc(m2);
        }
        __syncthreads();

        if (upper) {
            r1 += hist1[hc][e1];
            if (v2) r2 += hist2[hc][e2];
        }

        // ---- inline scatter: all zeros already in place (previous kernel) ----
        const size_t row = (size_t)t * (EE*CAP);
        const int p1 = s_c1[ch][e1] + r1;
        if (p1 < CAP) {
            const size_t o = row + (size_t)e1 * CAP + p1;
            out[o]        = 1.f;          // dispatch
            out[BNEC + o] = g_g1[t];      // combine
        }
        if (v2) {
            const int p2 = s_c2[ch][e2] + r2;
            if (p2 < CAP) {
                const size_t o = row + (size_t)e2 * CAP + p2;
                out[o]        = 1.f;
                out[BNEC + o] = g2v;
            }
        }
        __syncthreads();
    }
}

// ---------------- launch ----------------
extern "C" void kernel_launch(void* const* d_in, const int* in_sizes, int n_in,
                              void* d_out, int out_size) {
    const float* x = (const float*)d_in[0];   // [4,4096,1024] f32
    const float* w = (const float*)d_in[1];   // [1024,64] f32
    float* out = (float*)d_out;               // dispatch | combine | loss | z_loss

    fused_kernel<<<NB + NZB, 256>>>(x, w, out);
    scan_scatter_kernel<<<5, 1024>>>(out);
}